// round 15
// baseline (speedup 1.0000x reference)
#include <cuda_runtime.h>
#include <cuda_fp16.h>
#include <cstdint>

#define BDIM 1024
#define KDIM 2048
#define NDIM 4096

// Scratch (device globals — no allocation allowed)
__device__ __half g_xh[BDIM * KDIM];   // 2*x in fp16 [1024][2048]
__device__ __half g_wh[NDIM * KDIM];   // protos in fp16 (flat(Wt[2048][4096]))
__device__ float g_xsq[BDIM];
__device__ float g_pp[32][NDIM];       // psq partials: j = row-block within half

// ---------------------------------------------------------------------------
// Fused prep kernel: blocks 0..1023 pack x; blocks 1024..3071 transpose W.
// ---------------------------------------------------------------------------
__global__ void __launch_bounds__(256) prep_k(const float* __restrict__ x,
                                              const float* __restrict__ W) {
    const int b = blockIdx.x;
    const int t = threadIdx.x;

    if (b < BDIM) {
        const int row = b;
        const float4* xr = reinterpret_cast<const float4*>(x + (size_t)row * KDIM);
        float4 v0 = xr[t * 2];
        float4 v1 = xr[t * 2 + 1];
        float s = v0.x*v0.x + v0.y*v0.y + v0.z*v0.z + v0.w*v0.w
                + v1.x*v1.x + v1.y*v1.y + v1.z*v1.z + v1.w*v1.w;

        __half2 o0 = __floats2half2_rn(2.f*v0.x, 2.f*v0.y);
        __half2 o1 = __floats2half2_rn(2.f*v0.z, 2.f*v0.w);
        __half2 o2 = __floats2half2_rn(2.f*v1.x, 2.f*v1.y);
        __half2 o3 = __floats2half2_rn(2.f*v1.z, 2.f*v1.w);
        uint4 pk;
        pk.x = *reinterpret_cast<uint32_t*>(&o0);
        pk.y = *reinterpret_cast<uint32_t*>(&o1);
        pk.z = *reinterpret_cast<uint32_t*>(&o2);
        pk.w = *reinterpret_cast<uint32_t*>(&o3);
        reinterpret_cast<uint4*>(g_xh + (size_t)row * KDIM)[t] = pk;

        #pragma unroll
        for (int off = 16; off; off >>= 1) s += __shfl_xor_sync(0xffffffffu, s, off);
        __shared__ float ws[8];
        if ((t & 31) == 0) ws[t >> 5] = s;
        __syncthreads();
        if (t == 0) {
            float tot = 0.0f;
            #pragma unroll
            for (int j = 0; j < 8; j++) tot += ws[j];
            g_xsq[row] = tot;
        }
        return;
    }

    // transpose W 64x64 tile -> Wt fp16, psq partials
    __shared__ float tile[64][65];
    __shared__ float sqp[4][64];

    const int wb = b - BDIM;
    const int c0 = (wb & 31) * 64;    // W column base (KDIM/64 = 32)
    const int by = wb >> 5;           // 0..63
    const int r0 = by * 64;           // W row base

    #pragma unroll
    for (int i = 0; i < 4; i++) {
        int idx = t + i * 256;
        int row = idx >> 4;
        int c4  = (idx & 15) * 4;
        float4 v = *reinterpret_cast<const float4*>(
            W + (size_t)(r0 + row) * KDIM + c0 + c4);
        tile[row][c4 + 0] = v.x;
        tile[row][c4 + 1] = v.y;
        tile[row][c4 + 2] = v.z;
        tile[row][c4 + 3] = v.w;
    }
    __syncthreads();

    const int c   = t >> 2;
    const int seg = t & 3;
    __half hv[16];
    float sq = 0.0f;
    #pragma unroll
    for (int j = 0; j < 16; j++) {
        float v = tile[seg * 16 + j][c];
        hv[j] = __float2half_rn(v);
        sq += v * v;
    }
    {
        __half* dst = g_wh + (size_t)(c0 + c) * NDIM + r0 + seg * 16;
        *reinterpret_cast<uint4*>(dst)     = *reinterpret_cast<uint4*>(hv);
        *reinterpret_cast<uint4*>(dst + 8) = *reinterpret_cast<uint4*>(hv + 8);
    }
    sqp[seg][c] = sq;
    __syncthreads();

    if (seg == 0) {
        float tot = sqp[0][c] + sqp[1][c] + sqp[2][c] + sqp[3][c];
        int half = (by >= 32) ? 1 : 0;
        g_pp[by & 31][2 * (c0 + c) + half] = tot;
    }
}

// ---------------------------------------------------------------------------
// GEMM: BM=128, BN=256, BK=32, FIVE-stage cp.async, 256 threads (8 warps,
// 2Mx4N), warp tile 64x64, register double-buffered fragments, fp16 acc.
// ---------------------------------------------------------------------------
#define BK 32
#define STAGES 5
#define ROWB 80                            // bytes per padded smem row
#define A_BYTES (128 * ROWB)               // 10240
#define B_BYTES (256 * ROWB)               // 20480
#define SLOT_BYTES (A_BYTES + B_BYTES)     // 30720
#define TILE_OFF 1024                      // pbc[256] floats first
#define SMEM_TOTAL (TILE_OFF + STAGES * SLOT_BYTES)   // 154624

#define CP16(dst_u32, src_ptr) \
    asm volatile("cp.async.cg.shared.global [%0], [%1], 16;\n" :: "r"(dst_u32), "l"(src_ptr))
#define CP_COMMIT() asm volatile("cp.async.commit_group;\n" ::)
#define CP_WAITN()  asm volatile("cp.async.wait_group %0;\n" :: "n"(STAGES - 2))

#define LDSM_X4(r0, r1, r2, r3, addr) \
    asm volatile("ldmatrix.sync.aligned.m8n8.x4.shared.b16 {%0,%1,%2,%3}, [%4];\n" \
                 : "=r"(r0), "=r"(r1), "=r"(r2), "=r"(r3) : "r"(addr))

#define MMA16816H(d, a, b) \
    asm volatile("mma.sync.aligned.m16n8k16.row.col.f16.f16.f16.f16 " \
                 "{%0,%1},{%2,%3,%4,%5},{%6,%7},{%0,%1};\n" \
                 : "+r"(d[0]), "+r"(d[1]) \
                 : "r"(a[0]), "r"(a[1]), "r"(a[2]), "r"(a[3]), "r"(b[0]), "r"(b[1]))

#define LDSM_FRAGS(abuf, bbuf, sAs, sBs, ks) do {                              \
    _Pragma("unroll")                                                          \
    for (int mi = 0; mi < 4; ++mi) {                                           \
        uint32_t addr = (sAs) + aoff + (uint32_t)(mi * 16 * ROWB) + (uint32_t)((ks) * 32); \
        LDSM_X4((abuf)[mi][0], (abuf)[mi][1], (abuf)[mi][2], (abuf)[mi][3], addr); \
    }                                                                          \
    _Pragma("unroll")                                                          \
    for (int nj = 0; nj < 4; ++nj) {                                           \
        uint32_t addr = (sBs) + boff + (uint32_t)(nj * 16 * ROWB) + (uint32_t)((ks) * 32); \
        uint32_t r0_, r1_, r2_, r3_;                                           \
        LDSM_X4(r0_, r1_, r2_, r3_, addr);                                     \
        (bbuf)[2 * (nj)][0] = r0_;     (bbuf)[2 * (nj)][1] = r1_;              \
        (bbuf)[2 * (nj) + 1][0] = r2_; (bbuf)[2 * (nj) + 1][1] = r3_;          \
    }                                                                          \
} while (0)

#define MMA_BLOCK(abuf, bbuf) do {                                             \
    _Pragma("unroll")                                                          \
    for (int mi = 0; mi < 4; ++mi)                                             \
        _Pragma("unroll")                                                      \
        for (int ni = 0; ni < 8; ++ni)                                         \
            MMA16816H(acc[mi][ni], (abuf)[mi], (bbuf)[ni]);                    \
} while (0)

__global__ void __launch_bounds__(256, 1) gemm_k(const float* __restrict__ bias,
                                                 float* __restrict__ out) {
    extern __shared__ char smem[];
    const uint32_t sb = (uint32_t)__cvta_generic_to_shared(smem);
    float* pbc = reinterpret_cast<float*>(smem);     // [256] psq+bias
    const uint32_t sT = sb + TILE_OFF;

    const int t = threadIdx.x;
    const int bm = blockIdx.y * 128;
    const int bn = blockIdx.x * 256;

    const __half* gA = g_xh + (size_t)bm * KDIM;
    const __half* gB = g_wh + (size_t)bn * KDIM;   // flat(Wt) == protos rows

    auto load_slot = [&](int slot, int k0) {
        uint32_t abase = sT + slot * SLOT_BYTES;
        uint32_t bbase = abase + A_BYTES;
        #pragma unroll
        for (int i = 0; i < 2; i++) {
            int c = t + i * 256;
            int row = c >> 2, col = c & 3;
            CP16(abase + (uint32_t)(row * ROWB + col * 16),
                 gA + (size_t)row * KDIM + k0 + col * 8);
        }
        #pragma unroll
        for (int i = 0; i < 4; i++) {
            int c = t + i * 256;
            int row = c >> 2, col = c & 3;
            CP16(bbase + (uint32_t)(row * ROWB + col * 16),
                 gB + (size_t)row * KDIM + k0 + col * 8);
        }
    };

    // prologue cp.async FIRST — DMA in flight while pbc gathers below
    #pragma unroll
    for (int s = 0; s < STAGES - 1; s++) {
        load_slot(s, s * BK);
        CP_COMMIT();
    }

    // pbc[t] = bias + sum of 32 psq partials (overlapped with prologue DMA)
    {
        float acc0 = __ldg(&bias[bn + t]);
        #pragma unroll
        for (int j = 0; j < 32; j++) acc0 += g_pp[j][bn + t];
        pbc[t] = acc0;
    }

    const int warp = t >> 5, lane = t & 31;
    const int wm = warp & 1;   // 2 x 64 rows
    const int wn = warp >> 1;  // 4 x 64 cols

    const uint32_t aoff = (uint32_t)((wm * 64 + (lane & 15)) * ROWB + (lane >> 4) * 16);
    const uint32_t boff = (uint32_t)((wn * 64 + (lane & 7) + ((lane & 16) >> 1)) * ROWB
                                     + ((lane >> 3) & 1) * 16);

    uint32_t acc[4][8][2];
    #pragma unroll
    for (int mi = 0; mi < 4; ++mi)
        #pragma unroll
        for (int ni = 0; ni < 8; ++ni)
            acc[mi][ni][0] = acc[mi][ni][1] = 0u;

    uint32_t afr[2][4][4];
    uint32_t bfr[2][8][2];

    CP_WAITN();
    __syncthreads();

    LDSM_FRAGS(afr[0], bfr[0], sT, sT + A_BYTES, 0);

    const int NK = KDIM / BK;   // 64
    for (int kt = 0; kt < NK; ++kt) {
        const uint32_t sAs = sT + (kt % STAGES) * SLOT_BYTES;
        const uint32_t sBs = sAs + A_BYTES;

        LDSM_FRAGS(afr[1], bfr[1], sAs, sBs, 1);
        if (kt + STAGES - 1 < NK) load_slot((kt + STAGES - 1) % STAGES, (kt + STAGES - 1) * BK);
        CP_COMMIT();

        MMA_BLOCK(afr[0], bfr[0]);

        if (kt + 1 < NK) {
            CP_WAITN();
            __syncthreads();
            const uint32_t nAs = sT + ((kt + 1) % STAGES) * SLOT_BYTES;
            LDSM_FRAGS(afr[0], bfr[0], nAs, nAs + A_BYTES, 0);
        }

        MMA_BLOCK(afr[1], bfr[1]);
    }

    // epilogue: out = acc - xsq[row] - (psq+bias)[col]
    const int gid = lane >> 2, qid = lane & 3;
    #pragma unroll
    for (int mi = 0; mi < 4; ++mi) {
        int row0 = bm + wm * 64 + mi * 16 + gid;
        float xs0 = g_xsq[row0];
        float xs1 = g_xsq[row0 + 8];
        #pragma unroll
        for (int ni = 0; ni < 8; ++ni) {
            int lc = wn * 64 + ni * 8 + qid * 2;
            float pb0 = pbc[lc];
            float pb1 = pbc[lc + 1];
            float2 f0 = __half22float2(*reinterpret_cast<__half2*>(&acc[mi][ni][0]));
            float2 f1 = __half22float2(*reinterpret_cast<__half2*>(&acc[mi][ni][1]));
            float2 v0, v1;
            v0.x = f0.x - xs0 - pb0;
            v0.y = f0.y - xs0 - pb1;
            v1.x = f1.x - xs1 - pb0;
            v1.y = f1.y - xs1 - pb1;
            *reinterpret_cast<float2*>(out + (size_t)row0 * NDIM + bn + lc) = v0;
            *reinterpret_cast<float2*>(out + (size_t)(row0 + 8) * NDIM + bn + lc) = v1;
        }
    }
}

// ---------------------------------------------------------------------------
extern "C" void kernel_launch(void* const* d_in, const int* in_sizes, int n_in,
                              void* d_out, int out_size) {
    const float* x    = (const float*)d_in[0];
    const float* W    = (const float*)d_in[1];
    const float* bias = (const float*)d_in[2];
    float* out = (float*)d_out;

    cudaFuncSetAttribute(gemm_k, cudaFuncAttributeMaxDynamicSharedMemorySize, SMEM_TOTAL);

    prep_k<<<BDIM + (KDIM / 64) * (NDIM / 64), 256>>>(x, W);   // 3072 blocks
    gemm_k<<<dim3(NDIM / 256, BDIM / 128), 256, SMEM_TOTAL>>>(bias, out);
}

// round 16
// speedup vs baseline: 1.1026x; 1.1026x over previous
#include <cuda_runtime.h>
#include <cuda_fp16.h>
#include <cstdint>

#define BDIM 1024
#define KDIM 2048
#define NDIM 4096

// Scratch (device globals — no allocation allowed)
__device__ __half g_xh[BDIM * KDIM];   // 2*x in fp16 [1024][2048]
__device__ __half g_wh[NDIM * KDIM];   // protos in fp16 (flat(Wt[2048][4096]))
__device__ float g_xsq[BDIM];
__device__ float g_pp[32][NDIM];       // psq partials: j = row-block within half

// ---------------------------------------------------------------------------
// Fused prep kernel: blocks 0..1023 pack x; blocks 1024..3071 transpose W.
// ---------------------------------------------------------------------------
__global__ void __launch_bounds__(256) prep_k(const float* __restrict__ x,
                                              const float* __restrict__ W) {
    const int b = blockIdx.x;
    const int t = threadIdx.x;

    if (b < BDIM) {
        const int row = b;
        const float4* xr = reinterpret_cast<const float4*>(x + (size_t)row * KDIM);
        float4 v0 = xr[t * 2];
        float4 v1 = xr[t * 2 + 1];
        float s = v0.x*v0.x + v0.y*v0.y + v0.z*v0.z + v0.w*v0.w
                + v1.x*v1.x + v1.y*v1.y + v1.z*v1.z + v1.w*v1.w;

        __half2 o0 = __floats2half2_rn(2.f*v0.x, 2.f*v0.y);
        __half2 o1 = __floats2half2_rn(2.f*v0.z, 2.f*v0.w);
        __half2 o2 = __floats2half2_rn(2.f*v1.x, 2.f*v1.y);
        __half2 o3 = __floats2half2_rn(2.f*v1.z, 2.f*v1.w);
        uint4 pk;
        pk.x = *reinterpret_cast<uint32_t*>(&o0);
        pk.y = *reinterpret_cast<uint32_t*>(&o1);
        pk.z = *reinterpret_cast<uint32_t*>(&o2);
        pk.w = *reinterpret_cast<uint32_t*>(&o3);
        reinterpret_cast<uint4*>(g_xh + (size_t)row * KDIM)[t] = pk;

        #pragma unroll
        for (int off = 16; off; off >>= 1) s += __shfl_xor_sync(0xffffffffu, s, off);
        __shared__ float ws[8];
        if ((t & 31) == 0) ws[t >> 5] = s;
        __syncthreads();
        if (t == 0) {
            float tot = 0.0f;
            #pragma unroll
            for (int j = 0; j < 8; j++) tot += ws[j];
            g_xsq[row] = tot;
        }
        return;
    }

    // transpose W 64x64 tile -> Wt fp16, psq partials
    __shared__ float tile[64][65];
    __shared__ float sqp[4][64];

    const int wb = b - BDIM;
    const int c0 = (wb & 31) * 64;    // W column base (KDIM/64 = 32)
    const int by = wb >> 5;           // 0..63
    const int r0 = by * 64;           // W row base

    #pragma unroll
    for (int i = 0; i < 4; i++) {
        int idx = t + i * 256;
        int row = idx >> 4;
        int c4  = (idx & 15) * 4;
        float4 v = *reinterpret_cast<const float4*>(
            W + (size_t)(r0 + row) * KDIM + c0 + c4);
        tile[row][c4 + 0] = v.x;
        tile[row][c4 + 1] = v.y;
        tile[row][c4 + 2] = v.z;
        tile[row][c4 + 3] = v.w;
    }
    __syncthreads();

    const int c   = t >> 2;
    const int seg = t & 3;
    __half hv[16];
    float sq = 0.0f;
    #pragma unroll
    for (int j = 0; j < 16; j++) {
        float v = tile[seg * 16 + j][c];
        hv[j] = __float2half_rn(v);
        sq += v * v;
    }
    {
        __half* dst = g_wh + (size_t)(c0 + c) * NDIM + r0 + seg * 16;
        *reinterpret_cast<uint4*>(dst)     = *reinterpret_cast<uint4*>(hv);
        *reinterpret_cast<uint4*>(dst + 8) = *reinterpret_cast<uint4*>(hv + 8);
    }
    sqp[seg][c] = sq;
    __syncthreads();

    if (seg == 0) {
        float tot = sqp[0][c] + sqp[1][c] + sqp[2][c] + sqp[3][c];
        int half = (by >= 32) ? 1 : 0;
        g_pp[by & 31][2 * (c0 + c) + half] = tot;
    }
}

// ---------------------------------------------------------------------------
// GEMM (measured optimum, R11/R14): BM=128, BN=256, BK=32, 4-stage cp.async,
// 256 threads (8 warps, 2Mx4N), warp tile 64x64, register double-buffered
// fragments, fp16 accumulation. Prologue cp.async issued BEFORE pbc gather.
// ---------------------------------------------------------------------------
#define BK 32
#define STAGES 4
#define ROWB 80                            // bytes per padded smem row
#define A_BYTES (128 * ROWB)               // 10240
#define B_BYTES (256 * ROWB)               // 20480
#define SLOT_BYTES (A_BYTES + B_BYTES)     // 30720
#define TILE_OFF 1024                      // pbc[256] floats first
#define SMEM_TOTAL (TILE_OFF + STAGES * SLOT_BYTES)   // 123904

#define CP16(dst_u32, src_ptr) \
    asm volatile("cp.async.cg.shared.global [%0], [%1], 16;\n" :: "r"(dst_u32), "l"(src_ptr))
#define CP_COMMIT() asm volatile("cp.async.commit_group;\n" ::)
#define CP_WAIT2()  asm volatile("cp.async.wait_group 2;\n" ::)

#define LDSM_X4(r0, r1, r2, r3, addr) \
    asm volatile("ldmatrix.sync.aligned.m8n8.x4.shared.b16 {%0,%1,%2,%3}, [%4];\n" \
                 : "=r"(r0), "=r"(r1), "=r"(r2), "=r"(r3) : "r"(addr))

#define MMA16816H(d, a, b) \
    asm volatile("mma.sync.aligned.m16n8k16.row.col.f16.f16.f16.f16 " \
                 "{%0,%1},{%2,%3,%4,%5},{%6,%7},{%0,%1};\n" \
                 : "+r"(d[0]), "+r"(d[1]) \
                 : "r"(a[0]), "r"(a[1]), "r"(a[2]), "r"(a[3]), "r"(b[0]), "r"(b[1]))

#define LDSM_FRAGS(abuf, bbuf, sAs, sBs, ks) do {                              \
    _Pragma("unroll")                                                          \
    for (int mi = 0; mi < 4; ++mi) {                                           \
        uint32_t addr = (sAs) + aoff + (uint32_t)(mi * 16 * ROWB) + (uint32_t)((ks) * 32); \
        LDSM_X4((abuf)[mi][0], (abuf)[mi][1], (abuf)[mi][2], (abuf)[mi][3], addr); \
    }                                                                          \
    _Pragma("unroll")                                                          \
    for (int nj = 0; nj < 4; ++nj) {                                           \
        uint32_t addr = (sBs) + boff + (uint32_t)(nj * 16 * ROWB) + (uint32_t)((ks) * 32); \
        uint32_t r0_, r1_, r2_, r3_;                                           \
        LDSM_X4(r0_, r1_, r2_, r3_, addr);                                     \
        (bbuf)[2 * (nj)][0] = r0_;     (bbuf)[2 * (nj)][1] = r1_;              \
        (bbuf)[2 * (nj) + 1][0] = r2_; (bbuf)[2 * (nj) + 1][1] = r3_;          \
    }                                                                          \
} while (0)

#define MMA_BLOCK(abuf, bbuf) do {                                             \
    _Pragma("unroll")                                                          \
    for (int mi = 0; mi < 4; ++mi)                                             \
        _Pragma("unroll")                                                      \
        for (int ni = 0; ni < 8; ++ni)                                         \
            MMA16816H(acc[mi][ni], (abuf)[mi], (bbuf)[ni]);                    \
} while (0)

__global__ void __launch_bounds__(256, 1) gemm_k(const float* __restrict__ bias,
                                                 float* __restrict__ out) {
    extern __shared__ char smem[];
    const uint32_t sb = (uint32_t)__cvta_generic_to_shared(smem);
    float* pbc = reinterpret_cast<float*>(smem);     // [256] psq+bias
    const uint32_t sT = sb + TILE_OFF;

    const int t = threadIdx.x;
    const int bm = blockIdx.y * 128;
    const int bn = blockIdx.x * 256;

    const __half* gA = g_xh + (size_t)bm * KDIM;
    const __half* gB = g_wh + (size_t)bn * KDIM;   // flat(Wt) == protos rows

    auto load_slot = [&](int slot, int k0) {
        uint32_t abase = sT + slot * SLOT_BYTES;
        uint32_t bbase = abase + A_BYTES;
        #pragma unroll
        for (int i = 0; i < 2; i++) {
            int c = t + i * 256;
            int row = c >> 2, col = c & 3;
            CP16(abase + (uint32_t)(row * ROWB + col * 16),
                 gA + (size_t)row * KDIM + k0 + col * 8);
        }
        #pragma unroll
        for (int i = 0; i < 4; i++) {
            int c = t + i * 256;
            int row = c >> 2, col = c & 3;
            CP16(bbase + (uint32_t)(row * ROWB + col * 16),
                 gB + (size_t)row * KDIM + k0 + col * 8);
        }
    };

    // prologue cp.async FIRST — DMA in flight while pbc gathers below
    #pragma unroll
    for (int s = 0; s < STAGES - 1; s++) {
        load_slot(s, s * BK);
        CP_COMMIT();
    }

    // pbc[t] = bias + sum of 32 psq partials (overlapped with prologue DMA)
    {
        float acc0 = __ldg(&bias[bn + t]);
        #pragma unroll
        for (int j = 0; j < 32; j++) acc0 += g_pp[j][bn + t];
        pbc[t] = acc0;
    }

    const int warp = t >> 5, lane = t & 31;
    const int wm = warp & 1;   // 2 x 64 rows
    const int wn = warp >> 1;  // 4 x 64 cols

    const uint32_t aoff = (uint32_t)((wm * 64 + (lane & 15)) * ROWB + (lane >> 4) * 16);
    const uint32_t boff = (uint32_t)((wn * 64 + (lane & 7) + ((lane & 16) >> 1)) * ROWB
                                     + ((lane >> 3) & 1) * 16);

    uint32_t acc[4][8][2];
    #pragma unroll
    for (int mi = 0; mi < 4; ++mi)
        #pragma unroll
        for (int ni = 0; ni < 8; ++ni)
            acc[mi][ni][0] = acc[mi][ni][1] = 0u;

    uint32_t afr[2][4][4];
    uint32_t bfr[2][8][2];

    CP_WAIT2();
    __syncthreads();

    LDSM_FRAGS(afr[0], bfr[0], sT, sT + A_BYTES, 0);

    const int NK = KDIM / BK;   // 64
    for (int kt = 0; kt < NK; ++kt) {
        const uint32_t sAs = sT + (kt % STAGES) * SLOT_BYTES;
        const uint32_t sBs = sAs + A_BYTES;

        LDSM_FRAGS(afr[1], bfr[1], sAs, sBs, 1);
        if (kt + STAGES - 1 < NK) load_slot((kt + STAGES - 1) % STAGES, (kt + STAGES - 1) * BK);
        CP_COMMIT();

        MMA_BLOCK(afr[0], bfr[0]);

        if (kt + 1 < NK) {
            CP_WAIT2();
            __syncthreads();
            const uint32_t nAs = sT + ((kt + 1) % STAGES) * SLOT_BYTES;
            LDSM_FRAGS(afr[0], bfr[0], nAs, nAs + A_BYTES, 0);
        }

        MMA_BLOCK(afr[1], bfr[1]);
    }

    // epilogue: out = acc - xsq[row] - (psq+bias)[col]
    const int gid = lane >> 2, qid = lane & 3;
    #pragma unroll
    for (int mi = 0; mi < 4; ++mi) {
        int row0 = bm + wm * 64 + mi * 16 + gid;
        float xs0 = g_xsq[row0];
        float xs1 = g_xsq[row0 + 8];
        #pragma unroll
        for (int ni = 0; ni < 8; ++ni) {
            int lc = wn * 64 + ni * 8 + qid * 2;
            float pb0 = pbc[lc];
            float pb1 = pbc[lc + 1];
            float2 f0 = __half22float2(*reinterpret_cast<__half2*>(&acc[mi][ni][0]));
            float2 f1 = __half22float2(*reinterpret_cast<__half2*>(&acc[mi][ni][1]));
            float2 v0, v1;
            v0.x = f0.x - xs0 - pb0;
            v0.y = f0.y - xs0 - pb1;
            v1.x = f1.x - xs1 - pb0;
            v1.y = f1.y - xs1 - pb1;
            *reinterpret_cast<float2*>(out + (size_t)row0 * NDIM + bn + lc) = v0;
            *reinterpret_cast<float2*>(out + (size_t)(row0 + 8) * NDIM + bn + lc) = v1;
        }
    }
}

// ---------------------------------------------------------------------------
extern "C" void kernel_launch(void* const* d_in, const int* in_sizes, int n_in,
                              void* d_out, int out_size) {
    const float* x    = (const float*)d_in[0];
    const float* W    = (const float*)d_in[1];
    const float* bias = (const float*)d_in[2];
    float* out = (float*)d_out;

    cudaFuncSetAttribute(gemm_k, cudaFuncAttributeMaxDynamicSharedMemorySize, SMEM_TOTAL);

    prep_k<<<BDIM + (KDIM / 64) * (NDIM / 64), 256>>>(x, W);   // 3072 blocks
    gemm_k<<<dim3(NDIM / 256, BDIM / 128), 256, SMEM_TOTAL>>>(bias, out);
}